// round 7
// baseline (speedup 1.0000x reference)
#include <cuda_runtime.h>
#include <cuda_fp16.h>
#include <cstdint>

// ---------------- problem constants ----------------
#define B_      32
#define TI_     4096
#define D_      512
#define ROWS_   (B_ * TI_)     // 131072 context rows
#define MT_     64             // rows per CTA
#define NC_     256            // d-columns per CTA (d-split = 2)
#define KT_     32             // K per tile (halves)
#define NKT_    (D_ / KT_)     // 16 k-tiles
#define NTILES_ (ROWS_ / MT_)  // 2048

// ---------------- scratch (device globals; no allocation allowed) ----------------
__device__ float  g_qk[B_ * D_];            // folded q = output@Wq^T + bq + bk
__device__ float  g_scores[ROWS_];          // pre-softmax scores (atomic partials)
__device__ __half2 g_ctxh[ROWS_ * D_ / 2];  // fp16 context (134 MB)
__device__ __half2 g_wkh[D_ * D_ / 2];      // fp16 Wk

// ---------------- smem layout (bytes) ----------------
#define AS_BYTES 80                        // 32 halves (64B) + 16 pad, ldmatrix conflict-free
#define A_STAGE  (MT_ * AS_BYTES)          // 5120
#define B_STAGE  (NC_ * AS_BYTES)          // 20480
#define STAGE_SZ (A_STAGE + B_STAGE)       // 25600
#define OFF_A    0
#define OFF_B    A_STAGE
#define OFF_QK   (3 * STAGE_SZ)            // 76800
#define OFF_WV   (OFF_QK + 1024)
#define OFF_SP   (OFF_WV + 1024)           // 8 warps x 32 rows x 4B = 1024
#define SMEM_BYTES (OFF_SP + 1024)         // 79872 -> 2 CTAs/SM

__device__ __forceinline__ uint32_t smem_u32(const void* p) {
    uint32_t a;
    asm("{ .reg .u64 t; cvta.to.shared.u64 t, %1; cvt.u32.u64 %0, t; }" : "=r"(a) : "l"(p));
    return a;
}
__device__ __forceinline__ float tanh_fast(float x) {
    float t;
    asm("tanh.approx.f32 %0, %1;" : "=f"(t) : "f"(x));
    return t;
}

// ================= kernel 0: fp32 -> fp16 conversion of context and Wk =================
__global__ void cvt_kernel(const float* __restrict__ ctx, const float* __restrict__ wk) {
    long idx = (long)blockIdx.x * 256 + threadIdx.x;     // one float4 per thread
    const long NCTX4 = (long)ROWS_ * D_ / 4;
    if (idx < NCTX4) {
        float4 v = ((const float4*)ctx)[idx];
        g_ctxh[2 * idx]     = __float22half2_rn(make_float2(v.x, v.y));
        g_ctxh[2 * idx + 1] = __float22half2_rn(make_float2(v.z, v.w));
    } else {
        long j = idx - NCTX4;
        float4 v = ((const float4*)wk)[j];
        g_wkh[2 * j]     = __float22half2_rn(make_float2(v.x, v.y));
        g_wkh[2 * j + 1] = __float22half2_rn(make_float2(v.z, v.w));
    }
}

__global__ void dummy_kernel() {}

// ================= kernel 1: qk[b,d] = bq+bk + output[b]·Wq[d,:]; zero mix & scores ==========
__global__ void qk_kernel(const float* __restrict__ out_in, const float* __restrict__ Wq,
                          const float* __restrict__ bq, const float* __restrict__ bk,
                          float* __restrict__ mix) {
    int b = blockIdx.x, d = threadIdx.x;           // 512 threads, 32 blocks
    __shared__ float orow[D_];
    orow[d] = out_in[b * D_ + d];
    mix[b * D_ + d] = 0.0f;
    int gt = b * D_ + d;
    #pragma unroll
    for (int i = 0; i < ROWS_ / (B_ * D_); i++)
        g_scores[gt + i * B_ * D_] = 0.0f;
    __syncthreads();
    const float4* w = (const float4*)(Wq + (size_t)d * D_);
    float acc = bq[d] + bk[d];
    #pragma unroll 8
    for (int j = 0; j < D_ / 4; j++) {
        float4 t = w[j];
        acc = fmaf(t.x, orow[4*j], acc);
        acc = fmaf(t.y, orow[4*j+1], acc);
        acc = fmaf(t.z, orow[4*j+2], acc);
        acc = fmaf(t.w, orow[4*j+3], acc);
    }
    g_qk[b * D_ + d] = acc;
}

// ================= kernel 2: fused keys GEMM (fp16 m16n8k16) + tanh + Wv reduce ==============
// grid (2048, 2). 256 threads = 8 warps, 2(M)x4(N); warp tile 32x64. 3-stage cp.async.
// 2 CTAs/SM (smem 78KB, regs capped at 128).
__global__ void __launch_bounds__(256, 2)
scores_kernel(const float* __restrict__ Wv) {
    extern __shared__ char sm[];
    uint32_t sb = smem_u32(sm);
    int tid = threadIdx.x, lane = tid & 31, warp = tid >> 5;
    int wm = warp >> 2, wn = warp & 3;             // wm 0..1 (32 rows), wn 0..3 (64 cols)
    int tile = blockIdx.x, dc = blockIdx.y;
    int bidx = tile >> 6;                          // 64 tiles per batch
    size_t arow0 = (size_t)tile * MT_;
    const __half* Ag = (const __half*)g_ctxh + arow0 * D_;
    const __half* Bg = (const __half*)g_wkh + (size_t)dc * NC_ * D_;

    float* sqk = (float*)(sm + OFF_QK);
    float* swv = (float*)(sm + OFF_WV);
    sqk[tid] = g_qk[bidx * D_ + dc * NC_ + tid];
    swv[tid] = Wv[dc * NC_ + tid];

    float c[2][8][4];
    #pragma unroll
    for (int mi = 0; mi < 2; mi++)
        #pragma unroll
        for (int ni = 0; ni < 8; ni++)
            #pragma unroll
            for (int j = 0; j < 4; j++) c[mi][ni][j] = 0.0f;

    // per-lane ldmatrix base offsets (bytes within a stage)
    uint32_t a_off = (uint32_t)((wm * 32 + (lane & 15)) * AS_BYTES + (lane >> 4) * 16);
    uint32_t b_off = (uint32_t)((wn * 64 + ((lane >> 4) & 1) * 8 + (lane & 7)) * AS_BYTES
                                + ((lane >> 3) & 1) * 16);

    auto issue = [&](int kt) {
        int s = kt % 3;
        const __half* a = Ag + kt * KT_;
        uint32_t abase = sb + s * STAGE_SZ + OFF_A;
        {                                           // A: 256 granules / 256 thr
            int r = tid >> 2, cg = tid & 3;
            asm volatile("cp.async.cg.shared.global [%0], [%1], 16;"
                :: "r"(abase + r * AS_BYTES + cg * 16),
                   "l"(a + (size_t)r * D_ + cg * 8));
        }
        const __half* bsrc = Bg + kt * KT_;
        uint32_t bbase = sb + s * STAGE_SZ + OFF_B;
        #pragma unroll
        for (int i = 0; i < 4; i++) {               // B: 1024 granules / 256 thr
            int idx = tid + 256 * i;
            int r = idx >> 2, cg = idx & 3;
            asm volatile("cp.async.cg.shared.global [%0], [%1], 16;"
                :: "r"(bbase + r * AS_BYTES + cg * 16),
                   "l"(bsrc + (size_t)r * D_ + cg * 8));
        }
        asm volatile("cp.async.commit_group;");
    };

    issue(0);
    issue(1);
    #pragma unroll 1
    for (int kt = 0; kt < NKT_; kt++) {
        if (kt + 2 < NKT_) {
            issue(kt + 2);
            asm volatile("cp.async.wait_group 2;");
        } else {
            asm volatile("cp.async.wait_group 0;");
        }
        __syncthreads();
        int s = kt % 3;
        uint32_t abase = sb + s * STAGE_SZ + OFF_A + a_off;
        uint32_t bbase = sb + s * STAGE_SZ + OFF_B + b_off;
        #pragma unroll
        for (int q = 0; q < 2; q++) {               // 2 x k16 chunks
            uint32_t af[2][4], bf[4][4];
            #pragma unroll
            for (int mi = 0; mi < 2; mi++)
                asm volatile("ldmatrix.sync.aligned.m8n8.x4.shared.b16 {%0,%1,%2,%3}, [%4];"
                    : "=r"(af[mi][0]), "=r"(af[mi][1]), "=r"(af[mi][2]), "=r"(af[mi][3])
                    : "r"(abase + mi * (16 * AS_BYTES) + q * 32));
            #pragma unroll
            for (int g = 0; g < 4; g++)
                asm volatile("ldmatrix.sync.aligned.m8n8.x4.shared.b16 {%0,%1,%2,%3}, [%4];"
                    : "=r"(bf[g][0]), "=r"(bf[g][1]), "=r"(bf[g][2]), "=r"(bf[g][3])
                    : "r"(bbase + g * (16 * AS_BYTES) + q * 32));
            #pragma unroll
            for (int mi = 0; mi < 2; mi++)
                #pragma unroll
                for (int ni = 0; ni < 8; ni++) {
                    const uint32_t* bb = &bf[ni >> 1][(ni & 1) * 2];
                    asm volatile(
                        "mma.sync.aligned.m16n8k16.row.col.f32.f16.f16.f32 "
                        "{%0,%1,%2,%3}, {%4,%5,%6,%7}, {%8,%9}, {%0,%1,%2,%3};"
                        : "+f"(c[mi][ni][0]), "+f"(c[mi][ni][1]),
                          "+f"(c[mi][ni][2]), "+f"(c[mi][ni][3])
                        : "r"(af[mi][0]), "r"(af[mi][1]), "r"(af[mi][2]), "r"(af[mi][3]),
                          "r"(bb[0]), "r"(bb[1]));
                }
        }
        __syncthreads();
    }

    // ---- epilogue: score partial over this CTA's 256 d-cols ----
    float rs0[2] = {0, 0}, rs1[2] = {0, 0};
    #pragma unroll
    for (int mi = 0; mi < 2; mi++) {
        #pragma unroll
        for (int ni = 0; ni < 8; ni++) {
            int d0 = wn * 64 + ni * 8 + 2 * (lane & 3);
            float q0 = sqk[d0], q1 = sqk[d0 + 1];
            float w0 = swv[d0], w1 = swv[d0 + 1];
            rs0[mi] = fmaf(w0, tanh_fast(q0 + c[mi][ni][0]), rs0[mi]);
            rs0[mi] = fmaf(w1, tanh_fast(q1 + c[mi][ni][1]), rs0[mi]);
            rs1[mi] = fmaf(w0, tanh_fast(q0 + c[mi][ni][2]), rs1[mi]);
            rs1[mi] = fmaf(w1, tanh_fast(q1 + c[mi][ni][3]), rs1[mi]);
        }
        rs0[mi] += __shfl_xor_sync(0xffffffffu, rs0[mi], 1);
        rs0[mi] += __shfl_xor_sync(0xffffffffu, rs0[mi], 2);
        rs1[mi] += __shfl_xor_sync(0xffffffffu, rs1[mi], 1);
        rs1[mi] += __shfl_xor_sync(0xffffffffu, rs1[mi], 2);
    }
    float* sp = (float*)(sm + OFF_SP);             // [8 warps][32 rows]
    if ((lane & 3) == 0) {
        int g = lane >> 2;
        #pragma unroll
        for (int mi = 0; mi < 2; mi++) {
            sp[warp * 32 + mi * 16 + g]     = rs0[mi];
            sp[warp * 32 + mi * 16 + g + 8] = rs1[mi];
        }
    }
    __syncthreads();
    if (tid < MT_) {
        int wm2 = tid >> 5, rl = tid & 31;
        float s = sp[(wm2 * 4 + 0) * 32 + rl] + sp[(wm2 * 4 + 1) * 32 + rl]
                + sp[(wm2 * 4 + 2) * 32 + rl] + sp[(wm2 * 4 + 3) * 32 + rl];
        atomicAdd(&g_scores[arow0 + tid], s);
    }
}

// ================= kernel 3: softmax over Ti=4096 per batch =================
__device__ __forceinline__ float warpMax(float v) {
    #pragma unroll
    for (int o = 16; o; o >>= 1) v = fmaxf(v, __shfl_xor_sync(0xffffffffu, v, o));
    return v;
}
__device__ __forceinline__ float warpSum(float v) {
    #pragma unroll
    for (int o = 16; o; o >>= 1) v += __shfl_xor_sync(0xffffffffu, v, o);
    return v;
}

__global__ void softmax_kernel(float* __restrict__ attn) {
    int b = blockIdx.x, tid = threadIdx.x;         // 256 threads
    __shared__ float red[8];
    __shared__ float bc;
    const float* s = g_scores + b * TI_;
    float v[16];
    float mx = -3.0e38f;
    #pragma unroll
    for (int i = 0; i < 16; i++) { v[i] = s[tid + 256 * i]; mx = fmaxf(mx, v[i]); }
    mx = warpMax(mx);
    if ((tid & 31) == 0) red[tid >> 5] = mx;
    __syncthreads();
    if (tid < 32) { float m = (tid < 8) ? red[tid] : -3.0e38f; m = warpMax(m); if (tid == 0) bc = m; }
    __syncthreads();
    mx = bc;
    float sum = 0.0f;
    #pragma unroll
    for (int i = 0; i < 16; i++) { v[i] = __expf(v[i] - mx); sum += v[i]; }
    sum = warpSum(sum);
    if ((tid & 31) == 0) red[tid >> 5] = sum;
    __syncthreads();
    if (tid < 32) { float m = (tid < 8) ? red[tid] : 0.0f; m = warpSum(m); if (tid == 0) bc = m; }
    __syncthreads();
    float inv = 1.0f / bc;
    #pragma unroll
    for (int i = 0; i < 16; i++) attn[b * TI_ + tid + 256 * i] = v[i] * inv;
}

// ================= kernel 4: mix[b,d] = sum_t attn[b,t]*ctx16[b,t,d] (fp16 ctx) ==============
#define MIX_SPLIT 32
#define MIX_TPB   (TI_ / MIX_SPLIT)   // 128 rows per block

__global__ void mix_kernel(const float* __restrict__ attn, float* __restrict__ mix) {
    int b = blockIdx.y, z = blockIdx.x, d2 = threadIdx.x;  // 256 threads, 2 d-cols each
    __shared__ float sa[MIX_TPB];
    if (d2 < MIX_TPB) sa[d2] = attn[b * TI_ + z * MIX_TPB + d2];
    __syncthreads();
    const __half2* base = g_ctxh + ((size_t)b * TI_ + (size_t)z * MIX_TPB) * (D_ / 2) + d2;
    float ax = 0.0f, ay = 0.0f;
    #pragma unroll 8
    for (int t = 0; t < MIX_TPB; t++) {
        float2 f = __half22float2(base[(size_t)t * (D_ / 2)]);
        ax = fmaf(sa[t], f.x, ax);
        ay = fmaf(sa[t], f.y, ay);
    }
    atomicAdd(&mix[b * D_ + 2 * d2], ax);
    atomicAdd(&mix[b * D_ + 2 * d2 + 1], ay);
}

// ================= kernel 5: out = tanh([mix, output] @ Wo^T + bo) =================
__global__ void out_kernel(const float* __restrict__ mix, const float* __restrict__ out_in,
                           const float* __restrict__ Wo, const float* __restrict__ bo,
                           float* __restrict__ out) {
    int b = blockIdx.x, d = threadIdx.x;           // 512 threads
    __shared__ float comb[2 * D_];
    comb[d] = mix[b * D_ + d];
    comb[D_ + d] = out_in[b * D_ + d];
    __syncthreads();
    const float4* w = (const float4*)(Wo + (size_t)d * (2 * D_));
    float acc = bo[d];
    #pragma unroll 8
    for (int j = 0; j < (2 * D_) / 4; j++) {
        float4 t = w[j];
        acc = fmaf(t.x, comb[4*j], acc);
        acc = fmaf(t.y, comb[4*j+1], acc);
        acc = fmaf(t.z, comb[4*j+2], acc);
        acc = fmaf(t.w, comb[4*j+3], acc);
    }
    out[b * D_ + d] = tanhf(acc);
}

// ================= host launch =================
extern "C" void kernel_launch(void* const* d_in, const int* in_sizes, int n_in,
                              void* d_out, int out_size) {
    (void)in_sizes; (void)n_in; (void)out_size;
    const float* out_in  = (const float*)d_in[0];
    const float* context = (const float*)d_in[1];
    const float* Wq      = (const float*)d_in[2];
    const float* bq      = (const float*)d_in[3];
    const float* Wk      = (const float*)d_in[4];
    const float* bk      = (const float*)d_in[5];
    const float* Wv      = (const float*)d_in[6];
    const float* Wo      = (const float*)d_in[8];
    const float* bo      = (const float*)d_in[9];

    float* o_out  = (float*)d_out;                 // [32,1,512]
    float* o_attn = o_out + B_ * D_;               // [32,1,4096]
    float* o_mix  = o_attn + B_ * TI_;             // [32,1,512]

    // idempotent; host-side (not a stream op), safe under graph capture
    cudaFuncSetAttribute(scores_kernel, cudaFuncAttributeMaxDynamicSharedMemorySize, SMEM_BYTES);

    cvt_kernel<<<(ROWS_ * D_ + D_ * D_) / 4 / 256, 256>>>(context, Wk);
    qk_kernel<<<B_, D_>>>(out_in, Wq, bq, bk, o_mix);
    // 2 dummies: harness poison + cvt + qk + 2 dummies => scores is launch #6 for ncu -s 5
    dummy_kernel<<<1, 32>>>();
    dummy_kernel<<<1, 32>>>();
    scores_kernel<<<dim3(NTILES_, 2), 256, SMEM_BYTES>>>(Wv);
    softmax_kernel<<<B_, 256>>>(o_attn);
    mix_kernel<<<dim3(MIX_SPLIT, B_), 256>>>(o_attn, o_mix);
    out_kernel<<<B_, D_>>>(o_mix, out_in, Wo, bo, o_out);
}